// round 11
// baseline (speedup 1.0000x reference)
#include <cuda_runtime.h>
#include <cstdint>

#define NQ    32
#define KCB   1024
#define CDIM  8
#define DDIM  1024
#define BDIMS 8
#define TDIM  4096
#define TILE  32
#define NTH   512
#define NCOLS (BDIMS*TDIM)
#define BDT   (BDIMS*DDIM*TDIM)
#define NQBT  (NQ*NCOLS)

/* shared memory (floats): total 18528 fl = 74112 B */
#define SM_ZQM  0        /* 256 rows x 16 ull = 8192 fl */
#define SM_A    8192     /* 32 q x 289 = 9248 fl        */
#define SM_BD   17440    /* 512                         */
#define SM_BK   17952    /* 512                         */
#define SM_M    18464    /* 32                          */
#define SM_MP   18496    /* 16 ull = 32 fl              */
#define SM_TOT  18528
#define SM_BYTES (SM_TOT*4)

typedef unsigned long long ull;

__device__ ull   g_iwt2d[DDIM * 256];       /* [d][q*8+c] dup {w,w}        */
__device__ ull   g_ow2d [256 * DDIM];       /* [q*8+c][d] dup {w,w}        */
__device__ float g_cbT  [NQ * CDIM * KCB];  /* [q][c][k]                   */
__device__ float g_c2   [NQ * KCB];         /* |cb|^2                      */
__device__ float g_M    [NQ * NQ * 64];     /* [q2][p][c*8+cp] = -iw@ow    */
__device__ float g_Vc   [256];              /* [q*8+c] = iw^q . obpre^q    */
__device__ float g_obpre[NQ * DDIM];
__device__ float g_obsum[DDIM];

__device__ __forceinline__ ull f2x(float lo, float hi) {
    ull r;
    asm("mov.b64 %0, {%1, %2};" : "=l"(r)
        : "r"(__float_as_uint(lo)), "r"(__float_as_uint(hi)));
    return r;
}
__device__ __forceinline__ void upk(ull v, float& lo, float& hi) {
    unsigned a, b;
    asm("mov.b64 {%0, %1}, %2;" : "=r"(a), "=r"(b) : "l"(v));
    lo = __uint_as_float(a); hi = __uint_as_float(b);
}
#define FMA2(D,A,B,C) asm("fma.rn.f32x2 %0, %1, %2, %3;" : "=l"(D) : "l"(A), "l"(B), "l"(C))

/* ---------- prep 0: ob prefix sums ---------- */
__global__ void prep0_kernel(const float* __restrict__ ob)
{
    int d = blockIdx.x * blockDim.x + threadIdx.x;
    if (d < DDIM) {
        float run = 0.f;
        for (int p = 0; p < NQ; p++) {
            g_obpre[p * DDIM + d] = run;
            run += ob[p * DDIM + d];
        }
        g_obsum[d] = run;
    }
}

/* ---------- prep 1: duplicated transposes + |cb|^2 ---------- */
__global__ void prep1_kernel(const float* __restrict__ iw,
                             const float* __restrict__ ow,
                             const float* __restrict__ cb)
{
    int idx = blockIdx.x * blockDim.x + threadIdx.x;
    int stride = gridDim.x * blockDim.x;
    for (int i = idx; i < DDIM * 256; i += stride) {
        int d = i >> 8, r = i & 255, q = r >> 3, c = r & 7;
        float v = iw[(q << 13) + (c << 10) + d];
        g_iwt2d[i] = f2x(v, v);
    }
    for (int i = idx; i < 256 * DDIM; i += stride) {
        int r = i >> 10, d = i & 1023, q = r >> 3, c = r & 7;
        float v = ow[(q << 13) + (d << 3) + c];
        g_ow2d[i] = f2x(v, v);
    }
    for (int i = idx; i < NQ * CDIM * KCB; i += stride) {
        int q = i >> 13, r = i & 8191, c = r >> 10, k = r & 1023;
        g_cbT[i] = cb[(q << 13) + (k << 3) + c];
    }
    for (int k = idx; k < NQ * KCB; k += stride) {
        const float4* row = (const float4*)(cb + (size_t)k * 8);
        float4 a = row[0], b4 = row[1];
        float p = fmaf(a.x, a.x, fmaf(a.y, a.y, fmaf(a.z, a.z, a.w * a.w)));
        float o = fmaf(b4.x, b4.x, fmaf(b4.y, b4.y, fmaf(b4.z, b4.z, b4.w * b4.w)));
        g_c2[k] = p + o;
    }
}

/* ---------- prep 2: M[q2][p] = -(iw^q2 @ ow^p), p < q2 ---------- */
__global__ void prep2_kernel(const float* __restrict__ iw,
                             const float* __restrict__ ow)
{
    int q2 = blockIdx.x >> 5, p = blockIdx.x & 31;
    if (p >= q2) return;
    __shared__ float ps[512];
    int tid = threadIdx.x;
    int pair = tid & 63;
    int c = pair >> 3, cp = pair & 7;
    int slice = tid >> 6;
    const float* iwr = iw + (q2 << 13) + (c << 10) + slice * 128;
    const float* owr = ow + (p << 13) + cp + slice * 128 * 8;
    float s = 0.f;
    for (int d = 0; d < 128; d++) s = fmaf(iwr[d], owr[d * 8], s);
    ps[tid] = s;
    __syncthreads();
    if (tid < 64) {
        float t = 0.f;
        #pragma unroll
        for (int j = 0; j < 8; j++) t += ps[tid + j * 64];
        g_M[(q2 * 32 + p) * 64 + tid] = -t;
    }
}

/* ---------- prep 3: Vc[q][c] = iw^q[c] . obpre[q] ---------- */
__global__ void prep3_kernel(const float* __restrict__ iw)
{
    int q = blockIdx.x;
    __shared__ float ps[256];
    int tid = threadIdx.x;
    int c = tid >> 5, slice = tid & 31;
    const float* iwr = iw + (q << 13) + (c << 10) + slice * 32;
    const float* obr = g_obpre + (q << 10) + slice * 32;
    float s = 0.f;
    for (int d = 0; d < 32; d++) s = fmaf(iwr[d], obr[d], s);
    ps[tid] = s;
    __syncthreads();
    if (tid < 8) {
        float t = 0.f;
        #pragma unroll
        for (int j = 0; j < 32; j++) t += ps[tid * 32 + j];
        g_Vc[q * 8 + tid] = t;
    }
}

__global__ __launch_bounds__(NTH, 1)
void rvq_kernel(const float* __restrict__ z,
                const float* __restrict__ ibias,
                const float* __restrict__ cb,
                const int*   __restrict__ inlen,
                float* __restrict__ out,
                int wout, int widx, int wlen)
{
    extern __shared__ float sm[];
    ull*   zqm_u = (ull*)(sm + SM_ZQM);
    float* zqm_f = sm + SM_ZQM;
    float* A     = sm + SM_A;           /* [q][t*9+c], q stride 289 */
    float* bd_s  = sm + SM_BD;
    int*   bk_s  = (int*)(sm + SM_BK);
    float* m_s   = sm + SM_M;
    ull*   mp_u  = (ull*)(sm + SM_MP);

    const int tid  = threadIdx.x;
    const int lane = tid & 31;
    const int w    = tid >> 5;          /* 0..15 */

    const int col0 = blockIdx.x * TILE;
    const int b    = col0 >> 12;
    const int t0   = col0 & (TDIM - 1);
    const int len  = inlen[b];

    const float* zb = z + (size_t)b * DDIM * TDIM + t0;

    if (tid < TILE) m_s[tid] = ((t0 + tid) < len) ? 1.0f : 0.0f;
    if (tid < 16) {
        float a = ((t0 + 2 * tid)     < len) ? 1.0f : 0.0f;
        float c = ((t0 + 2 * tid + 1) < len) ? 1.0f : 0.0f;
        mp_u[tid] = f2x(a, c);
    }

    /* ====== E0: A[q][t][c] = iw.(z*m) + ib - m*Vc ; warp = 16 rows ====== */
    {
        const int tp = lane & 15, rh = lane >> 4;
        const int rb = w * 16 + rh * 8;         /* rows rb..rb+7, q = 2w+rh */
        const int q  = 2 * w + rh;
        const float mlo = ((t0 + 2 * tp)     < len) ? 1.0f : 0.0f;
        const float mhi = ((t0 + 2 * tp + 1) < len) ? 1.0f : 0.0f;
        ull v[8];
        #pragma unroll
        for (int j = 0; j < 8; j++) v[j] = 0ull;
        const ull* iwt = g_iwt2d + rb;
        const float* zrow = zb + 2 * tp;
        #pragma unroll 4
        for (int d = 0; d < 1024; d++) {
            float2 zv = *(const float2*)(zrow + (size_t)d * TDIM);
            ull rr = f2x(zv.x * mlo, zv.y * mhi);
            ulonglong2 wa = *(const ulonglong2*)(iwt + d * 256);
            ulonglong2 wb = *(const ulonglong2*)(iwt + d * 256 + 2);
            ulonglong2 wc = *(const ulonglong2*)(iwt + d * 256 + 4);
            ulonglong2 wd = *(const ulonglong2*)(iwt + d * 256 + 6);
            FMA2(v[0], wa.x, rr, v[0]);
            FMA2(v[1], wa.y, rr, v[1]);
            FMA2(v[2], wb.x, rr, v[2]);
            FMA2(v[3], wb.y, rr, v[3]);
            FMA2(v[4], wc.x, rr, v[4]);
            FMA2(v[5], wc.y, rr, v[5]);
            FMA2(v[6], wd.x, rr, v[6]);
            FMA2(v[7], wd.y, rr, v[7]);
        }
        float* Aq = A + q * 289;
        #pragma unroll
        for (int j = 0; j < 8; j++) {
            float lo, hi; upk(v[j], lo, hi);
            float ibv = ibias[q * 8 + j];
            float vc  = g_Vc[q * 8 + j];
            Aq[(2 * tp)     * 9 + j] = lo + ibv - mlo * vc;
            Aq[(2 * tp + 1) * 9 + j] = hi + ibv - mhi * vc;
        }
    }
    __syncthreads();

    /* ================== scan: P2 + select + scatter ================== */
    for (int q = 0; q < NQ; q++) {
        /* P2: warp w scans k in [64w,64w+64), lanes = t; cbT via L1 */
        {
            int t = lane;
            const float* Aq = A + q * 289 + t * 9;
            ull ed[8];
            #pragma unroll
            for (int c = 0; c < 8; c++) {
                float e = Aq[c];
                ed[c] = f2x(e, e);
            }
            const ull n2 = f2x(-2.0f, -2.0f);
            const float* cbt = g_cbT + ((size_t)q << 13);
            const float* c2g = g_c2 + ((size_t)q << 10);
            float best = 3.402823466e38f;
            int bk = 0;
            const int kb = w << 6;
            #pragma unroll 4
            for (int i = 0; i < 16; i++) {
                int k = kb + (i << 2);
                ull sA = 0ull, sB = 0ull;
                #pragma unroll
                for (int c = 0; c < 8; c++) {
                    ulonglong2 cv = *(const ulonglong2*)(cbt + c * 1024 + k);
                    FMA2(sA, cv.x, ed[c], sA);
                    FMA2(sB, cv.y, ed[c], sB);
                }
                ulonglong2 c2v = *(const ulonglong2*)(c2g + k);
                ull bA, bB;
                FMA2(bA, sA, n2, c2v.x);
                FMA2(bB, sB, n2, c2v.y);
                float da, db, dc, dd;
                upk(bA, da, db); upk(bB, dc, dd);
                if (da < best) { best = da; bk = k;     }
                if (db < best) { best = db; bk = k + 1; }
                if (dc < best) { best = dc; bk = k + 2; }
                if (dd < best) { best = dd; bk = k + 3; }
            }
            bd_s[w * 32 + t] = best;
            bk_s[w * 32 + t] = bk;
        }
        __syncthreads();

        /* select: final argmin + stage zqm row block q (masked) */
        if (tid < TILE) {
            int t = tid;
            float best = bd_s[t];
            int bk = bk_s[t];
            #pragma unroll
            for (int kc = 1; kc < 16; kc++) {
                float d2 = bd_s[kc * 32 + t];
                if (d2 < best) { best = d2; bk = bk_s[kc * 32 + t]; }
            }
            if (widx) out[BDT + q * NCOLS + col0 + t] = (float)bk;
            float mt = m_s[t];
            const float4* cr = (const float4*)(cb + (((size_t)q << 10) + bk) * 8);
            float4 ca = cr[0], cb4 = cr[1];
            float* zp = zqm_f + (q * 8) * 32 + t;
            zp[0 * 32] = ca.x * mt;  zp[1 * 32] = ca.y * mt;
            zp[2 * 32] = ca.z * mt;  zp[3 * 32] = ca.w * mt;
            zp[4 * 32] = cb4.x * mt; zp[5 * 32] = cb4.y * mt;
            zp[6 * 32] = cb4.z * mt; zp[7 * 32] = cb4.w * mt;
        }
        __syncthreads();

        /* scatter: A[q2] += M~[q2][q] . zqm^q (M~ pre-negated) */
        if (q < NQ - 1) {
            int nf = (NQ - 1 - q) * 8;
            float zq8[8];
            #pragma unroll
            for (int cp = 0; cp < 8; cp++)
                zq8[cp] = zqm_f[(q * 8 + cp) * 32 + lane];
            for (int idx = w; idx < nf; idx += 16) {
                int q2 = q + 1 + (idx >> 3), c = idx & 7;
                const float* Mr = g_M + (q2 * 32 + q) * 64 + c * 8;
                float4 m0 = *(const float4*)Mr;
                float4 m1 = *(const float4*)(Mr + 4);
                float s = m0.x * zq8[0];
                s = fmaf(m0.y, zq8[1], s);
                s = fmaf(m0.z, zq8[2], s);
                s = fmaf(m0.w, zq8[3], s);
                s = fmaf(m1.x, zq8[4], s);
                s = fmaf(m1.y, zq8[5], s);
                s = fmaf(m1.z, zq8[6], s);
                s = fmaf(m1.w, zq8[7], s);
                A[q2 * 289 + lane * 9 + c] += s;
            }
            __syncthreads();
        }
    }

    /* ====== qout: out[d][t] = sum_r ow2d[r][d]*zqm[r][t] + obsum[d]*m ==== */
    {
        ull mm[16];
        #pragma unroll
        for (int e = 0; e < 16; e++) mm[e] = mp_u[e];
        #pragma unroll
        for (int pass = 0; pass < 2; pass++) {
            int d = pass * 512 + w * 32 + lane;
            ull acc[16];
            #pragma unroll
            for (int e = 0; e < 16; e++) acc[e] = 0ull;
            const ull* owc = g_ow2d + d;
            #pragma unroll 8
            for (int r = 0; r < 256; r++) {
                ull wd = owc[(size_t)r * 1024];
                const ulonglong2* zr = (const ulonglong2*)(zqm_u + r * 16);
                #pragma unroll
                for (int e = 0; e < 8; e++) {
                    ulonglong2 zz = zr[e];
                    FMA2(acc[2 * e],     wd, zz.x, acc[2 * e]);
                    FMA2(acc[2 * e + 1], wd, zz.y, acc[2 * e + 1]);
                }
            }
            if (wout) {
                float ov = g_obsum[d];
                ull od = f2x(ov, ov);
                float* orow = out + (size_t)b * DDIM * TDIM + (size_t)d * TDIM + t0;
                #pragma unroll
                for (int e = 0; e < 16; e += 2) {
                    FMA2(acc[e],     od, mm[e],     acc[e]);
                    FMA2(acc[e + 1], od, mm[e + 1], acc[e + 1]);
                    float x0, x1, x2, x3;
                    upk(acc[e], x0, x1); upk(acc[e + 1], x2, x3);
                    *(float4*)(orow + e * 2) = make_float4(x0, x1, x2, x3);
                }
            }
        }
    }
    if (wlen && blockIdx.x == 0 && tid < BDIMS)
        out[BDT + NQBT + tid] = (float)inlen[tid];
}

extern "C" void kernel_launch(void* const* d_in, const int* in_sizes, int n_in,
                              void* d_out, int out_size)
{
    const float* z   = (const float*)d_in[0];
    const float* iw  = (const float*)d_in[1];
    const float* ib  = (const float*)d_in[2];
    const float* ow  = (const float*)d_in[3];
    const float* ob  = (const float*)d_in[4];
    const float* cbk = (const float*)d_in[5];
    const int* inlen = (const int*)d_in[6];
    float* out = (float*)d_out;

    cudaFuncSetAttribute(rvq_kernel, cudaFuncAttributeMaxDynamicSharedMemorySize, SM_BYTES);

    int wout = (out_size >= BDT) ? 1 : 0;
    int widx = (out_size >= BDT + NQBT) ? 1 : 0;
    int wlen = (out_size >= BDT + NQBT + BDIMS) ? 1 : 0;

    prep0_kernel<<<4, 256>>>(ob);
    prep1_kernel<<<256, 512>>>(iw, ow, cbk);
    prep2_kernel<<<NQ * NQ, 512>>>(iw, ow);
    prep3_kernel<<<NQ, 256>>>(iw);
    rvq_kernel<<<NCOLS / TILE, NTH, SM_BYTES>>>(z, ib, cbk, inlen,
                                               out, wout, widx, wlen);
}

// round 13
// speedup vs baseline: 1.6571x; 1.6571x over previous
#include <cuda_runtime.h>
#include <cstdint>

#define NQ    32
#define KCB   1024
#define CDIM  8
#define DDIM  1024
#define BDIMS 8
#define TDIM  4096
#define TILE  32
#define NTH   512
#define NCOLS (BDIMS*TDIM)          /* 32768 */
#define BDT   (BDIMS*DDIM*TDIM)     /* 33554432 */
#define NQBT  (NQ*NCOLS)            /* 1048576 */

/* shared memory offsets (floats) */
#define SM_R    0                   /* 1024 x 32 residual, swizzled float4  */
#define SM_W    32768               /* 8 x 1024 : iw (P1) then owT (P3)     */
#define SM_OB   40960               /* 1024                                 */
#define SM_CBT  41984               /* cbT: 8 x 1024                        */
#define SM_C2   50176               /* 1024                                 */
#define SM_ZE   51200               /* 32 x 9                               */
#define SM_PART 51488               /* 16 w x 32 ull = 1024 floats          */
#define SM_ZQP  52512               /* 256 floats                           */
#define SM_M    52768               /* 32                                   */
#define SM_MP   52800               /* 32                                   */
#define SM_BD   52832               /* 512                                  */
#define SM_BK   53344               /* 512                                  */
#define SM_TOT  53856
#define SM_BYTES (SM_TOT*4)

typedef unsigned long long ull;

__device__ float g_owT[NQ * CDIM * DDIM];   /* [q][c][d] */
__device__ float g_cbT[NQ * CDIM * KCB];    /* [q][c][k] */
__device__ float g_c2 [NQ * KCB];           /* |cb|^2    */

__device__ __forceinline__ ull f2x(float lo, float hi) {
    ull r;
    asm("mov.b64 %0, {%1, %2};" : "=l"(r)
        : "r"(__float_as_uint(lo)), "r"(__float_as_uint(hi)));
    return r;
}
__device__ __forceinline__ void upk(ull v, float& lo, float& hi) {
    unsigned a, b;
    asm("mov.b64 {%0, %1}, %2;" : "=r"(a), "=r"(b) : "l"(v));
    lo = __uint_as_float(a); hi = __uint_as_float(b);
}
#define FMA2(D,A,B,C) asm("fma.rn.f32x2 %0, %1, %2, %3;" : "=l"(D) : "l"(A), "l"(B), "l"(C))
#define ADD2(D,A,B)   asm("add.rn.f32x2 %0, %1, %2;"     : "=l"(D) : "l"(A), "l"(B))

__device__ __forceinline__ unsigned s2u(const void* p) {
    unsigned a;
    asm("{ .reg .u64 t; cvta.to.shared.u64 t, %1; cvt.u32.u64 %0, t; }"
        : "=r"(a) : "l"(p));
    return a;
}
__device__ __forceinline__ void cpa16(unsigned saddr, const void* g) {
    asm volatile("cp.async.cg.shared.global [%0], [%1], 16;" :: "r"(saddr), "l"(g));
}
#define CPA_COMMIT() asm volatile("cp.async.commit_group;")
#define CPA_WAIT0()  asm volatile("cp.async.wait_group 0;")
#define CPA_WAIT1()  asm volatile("cp.async.wait_group 1;")

__global__ void prep_kernel(const float* __restrict__ ow,
                            const float* __restrict__ cb)
{
    int idx = blockIdx.x * blockDim.x + threadIdx.x;
    int stride = gridDim.x * blockDim.x;
    for (int i = idx; i < NQ * CDIM * DDIM; i += stride) {
        int q = i >> 13, r = i & 8191, c = r >> 10, d = r & 1023;
        g_owT[i] = ow[(q << 13) + (d << 3) + c];
    }
    for (int i = idx; i < NQ * CDIM * KCB; i += stride) {
        int q = i >> 13, r = i & 8191, c = r >> 10, k = r & 1023;
        g_cbT[i] = cb[(q << 13) + (k << 3) + c];
    }
    for (int k = idx; k < NQ * KCB; k += stride) {
        const float4* row = (const float4*)(cb + (size_t)k * 8);
        float4 a = row[0], b4 = row[1];
        float p = fmaf(a.x, a.x, fmaf(a.y, a.y, fmaf(a.z, a.z, a.w * a.w)));
        float o = fmaf(b4.x, b4.x, fmaf(b4.y, b4.y, fmaf(b4.z, b4.z, b4.w * b4.w)));
        g_c2[k] = p + o;
    }
}

__global__ __launch_bounds__(NTH, 1)
void rvq_kernel(const float* __restrict__ z,
                const float* __restrict__ iw,
                const float* __restrict__ ibias,
                const float* __restrict__ obias,
                const float* __restrict__ cb,
                const int*   __restrict__ inlen,
                float* __restrict__ out,
                int wout, int widx, int wlen)
{
    extern __shared__ float sm[];
    float* r_s   = sm + SM_R;
    float* w_s   = sm + SM_W;
    float* ob_s  = sm + SM_OB;
    float* cbt_s = sm + SM_CBT;
    float* c2_s  = sm + SM_C2;
    float* ze_s  = sm + SM_ZE;
    ull*   partu = (ull*)(sm + SM_PART);
    float* partf = sm + SM_PART;
    ull*   zqp_u = (ull*)(sm + SM_ZQP);
    float* zqp_f = sm + SM_ZQP;
    float* m_s   = sm + SM_M;
    ull*   mp_u  = (ull*)(sm + SM_MP);
    float* mp_f  = sm + SM_MP;
    float* bd_s  = sm + SM_BD;
    int*   bk_s  = (int*)(sm + SM_BK);
    float4* R4   = (float4*)r_s;

    const unsigned sw_u   = s2u(w_s);
    const unsigned scbt_u = s2u(cbt_s);
    const unsigned sc2_u  = s2u(c2_s);
    const unsigned sob_u  = s2u(ob_s);

    const int tid  = threadIdx.x;
    const int lane = tid & 31;
    const int w    = tid >> 5;          /* 0..15 */
    /* P1 decomposition: 4 t-groups x 4 d-slices */
    const int tg1  = w >> 2;            /* 0..3 : 8-t group  */
    const int dg1  = w & 3;             /* 0..3 : 256-d slice */
    const int tqa1 = tg1 << 1, tqb1 = tqa1 + 1;
    /* P3 decomposition (R8-proven): 8 t-groups x 2 d-slices */
    const int tg3  = w >> 1;            /* 0..7 : 4-t quad   */
    const int dg3  = w & 1;             /* 0..1 : 512-d slice */

    const int col0 = blockIdx.x * TILE;
    const int b    = col0 >> 12;
    const int t0   = col0 & (TDIM - 1);
    const int len  = inlen[b];

    const float* zb = z + (size_t)b * DDIM * TDIM + t0;

    /* staging: 32KB arrays = 4 x 16B per thread; 4KB = 256 x 16B */
    #define STAGE32(dstu, src) do {                                        \
        const float4* _g = (const float4*)(src);                           \
        cpa16((dstu) + tid * 16,                (const void*)(_g + tid));  \
        cpa16((dstu) + (tid + 512) * 16,  (const void*)(_g + tid + 512));  \
        cpa16((dstu) + (tid + 1024) * 16, (const void*)(_g + tid + 1024)); \
        cpa16((dstu) + (tid + 1536) * 16, (const void*)(_g + tid + 1536)); \
    } while (0)
    #define STAGE4(dstu, src) do {                                         \
        if (tid < 256) {                                                   \
            const float4* _g = (const float4*)(src);                       \
            cpa16((dstu) + tid * 16, (const void*)(_g + tid));             \
        }                                                                  \
    } while (0)

    if (tid < TILE) {
        int t = tid;
        float m = ((t0 + t) < len) ? 1.0f : 0.0f;
        m_s[t] = m;
        int tgg = t >> 2, tj = t & 3, tp = tj >> 1, h = tj & 1;
        mp_f[(tgg * 2 + tp) * 2 + h] = -m;
    }

    /* kick q=0 staging while we fill R */
    STAGE32(sw_u,   iw);
    STAGE32(scbt_u, g_cbT);
    STAGE4(sc2_u,   g_c2);
    STAGE4(sob_u,   obias);
    CPA_COMMIT();

    /* ---- init residual = z * mask (swizzled float4 over t-quads) ---- */
    #pragma unroll
    for (int it = 0; it < 16; it++) {
        int i = tid + it * NTH;
        int d = i >> 3, tq = i & 7;
        float4 v = *(const float4*)(zb + (size_t)d * TDIM + (tq << 2));
        int tb = t0 + (tq << 2);
        v.x = (tb + 0 < len) ? v.x : 0.0f;
        v.y = (tb + 1 < len) ? v.y : 0.0f;
        v.z = (tb + 2 < len) ? v.z : 0.0f;
        v.w = (tb + 3 < len) ? v.w : 0.0f;
        R4[d * 8 + (tq ^ (d & 7))] = v;
    }

    for (int q = 0; q < NQ; q++) {
        CPA_WAIT0();
        __syncthreads();

        /* ====== phase 1 (packed, 4tg x 4dg): 8 t x 256 d per warp ====== */
        {
            ull v[32];
            #pragma unroll
            for (int i = 0; i < 32; i++) v[i] = 0ull;

            #pragma unroll 2
            for (int i = 0; i < 8; i++) {
                int d = dg1 * 256 + (i << 5) + lane;
                ulonglong2 rA = *(const ulonglong2*)&R4[d * 8 + (tqa1 ^ (d & 7))];
                ulonglong2 rB = *(const ulonglong2*)&R4[d * 8 + (tqb1 ^ (d & 7))];
                #pragma unroll
                for (int c = 0; c < 8; c++) {
                    float wv = w_s[c * 1024 + d];
                    ull wd = f2x(wv, wv);
                    FMA2(v[c * 4 + 0], wd, rA.x, v[c * 4 + 0]);   /* pair 4tg1+0 */
                    FMA2(v[c * 4 + 1], wd, rA.y, v[c * 4 + 1]);   /* pair 4tg1+1 */
                    FMA2(v[c * 4 + 2], wd, rB.x, v[c * 4 + 2]);   /* pair 4tg1+2 */
                    FMA2(v[c * 4 + 3], wd, rB.y, v[c * 4 + 3]);   /* pair 4tg1+3 */
                }
            }
            /* split-exchange: 32 ull over 32 lanes -> lane l holds item l */
            int n = 32;
            #pragma unroll
            for (int off = 16; off >= 1; off >>= 1) {
                n >>= 1;
                bool hi = (lane & off) != 0;
                #pragma unroll
                for (int i = 0; i < 16; i++) {
                    if (i < n) {
                        ull send = hi ? v[i] : v[i + n];
                        ull recv = __shfl_xor_sync(0xffffffffu, send, off);
                        ull keep = hi ? v[i + n] : v[i];
                        ADD2(v[i], keep, recv);
                    }
                }
            }
            partu[w * 32 + lane] = v[0];
        }
        __syncthreads();

        /* ---- issue ow[q] async (w_s free), combine partials -> ze ---- */
        STAGE32(sw_u, g_owT + ((size_t)q << 13));
        CPA_COMMIT();
        if (tid < 256) {
            int t = tid >> 3, c = tid & 7;
            int tgg = t >> 3, rem = t & 7, j = rem >> 1, h = rem & 1;
            int item = c * 4 + j;
            float s = partf[((tgg * 4 + 0) * 32 + item) * 2 + h]
                    + partf[((tgg * 4 + 1) * 32 + item) * 2 + h]
                    + partf[((tgg * 4 + 2) * 32 + item) * 2 + h]
                    + partf[((tgg * 4 + 3) * 32 + item) * 2 + h]
                    + ibias[q * CDIM + c];
            ze_s[t * 9 + c] = s;
        }
        __syncthreads();

        /* ====== phase 2 (packed k-quads): lane = t, warp = 64 k's ====== */
        {
            int t = lane;
            ull ed[8];
            #pragma unroll
            for (int c = 0; c < 8; c++) {
                float e = ze_s[t * 9 + c];
                ed[c] = f2x(e, e);
            }
            const ull n2 = f2x(-2.0f, -2.0f);
            float best = 3.402823466e38f;
            int bk = 0;
            const int kb = w << 6;
            #pragma unroll 4
            for (int i = 0; i < 16; i++) {
                int k = kb + (i << 2);
                ull sA = 0ull, sB = 0ull;
                #pragma unroll
                for (int c = 0; c < 8; c++) {
                    ulonglong2 cv = *(const ulonglong2*)(cbt_s + c * 1024 + k);
                    FMA2(sA, cv.x, ed[c], sA);
                    FMA2(sB, cv.y, ed[c], sB);
                }
                ulonglong2 c2v = *(const ulonglong2*)(c2_s + k);
                ull bA, bB;
                FMA2(bA, sA, n2, c2v.x);   /* dist = c2 - 2s (e2 rank-invariant) */
                FMA2(bB, sB, n2, c2v.y);
                float da, db, dc, dd;
                upk(bA, da, db); upk(bB, dc, dd);
                if (da < best) { best = da; bk = k;     }
                if (db < best) { best = db; bk = k + 1; }
                if (dc < best) { best = dc; bk = k + 2; }
                if (dd < best) { best = dd; bk = k + 3; }
            }
            bd_s[w * 32 + t] = best;
            bk_s[w * 32 + t] = bk;
        }
        __syncthreads();

        /* ---- prefetch cbT/c2 for q+1 (region idle), select, wait ow ---- */
        if (q + 1 < NQ) {
            STAGE32(scbt_u, g_cbT + ((size_t)(q + 1) << 13));
            STAGE4(sc2_u,   g_c2 + ((size_t)(q + 1) << 10));
        }
        CPA_COMMIT();
        if (tid < TILE) {
            int t = tid;
            float best = bd_s[t];
            int bk = bk_s[t];
            #pragma unroll
            for (int kc = 1; kc < 16; kc++) {
                float d2 = bd_s[kc * 32 + t];
                if (d2 < best) { best = d2; bk = bk_s[kc * 32 + t]; }
            }
            if (widx) out[BDT + q * NCOLS + col0 + t] = (float)bk;
            float mt = m_s[t];
            const float4* cr = (const float4*)(cb + (((size_t)q << 10) + bk) * 8);
            float4 ca = cr[0], cb4 = cr[1];
            int tgg = t >> 2, tj = t & 3, tp = tj >> 1, h = tj & 1;
            float* zp = zqp_f + ((tgg * 2 + tp) * 8) * 2 + h;
            zp[0]  = -ca.x * mt;  zp[2]  = -ca.y * mt;
            zp[4]  = -ca.z * mt;  zp[6]  = -ca.w * mt;
            zp[8]  = -cb4.x * mt; zp[10] = -cb4.y * mt;
            zp[12] = -cb4.z * mt; zp[14] = -cb4.w * mt;
        }
        CPA_WAIT1();            /* ow[q] done; cbT[q+1] may stay in flight */
        __syncthreads();

        /* ====== phase 3 (packed, R8 8tg x 2dg): r -= ow.zq + ob*m ====== */
        {
            ull zqA[8], zqB[8];
            #pragma unroll
            for (int c = 0; c < 8; c++) {
                zqA[c] = zqp_u[(tg3 * 2 + 0) * 8 + c];
                zqB[c] = zqp_u[(tg3 * 2 + 1) * 8 + c];
            }
            const ull nmA = mp_u[tg3 * 2 + 0];
            const ull nmB = mp_u[tg3 * 2 + 1];
            #pragma unroll 4
            for (int i = 0; i < 16; i++) {
                int d = dg3 * 512 + lane + (i << 5);
                int slot = d * 8 + (tg3 ^ (d & 7));
                ulonglong2 r = *(const ulonglong2*)&R4[slot];
                float obv = ob_s[d];
                ull obd2 = f2x(obv, obv);
                FMA2(r.x, obd2, nmA, r.x);
                FMA2(r.y, obd2, nmB, r.y);
                #pragma unroll
                for (int c = 0; c < 8; c++) {
                    float wv = w_s[c * 1024 + d];
                    ull wd = f2x(wv, wv);
                    FMA2(r.x, wd, zqA[c], r.x);
                    FMA2(r.y, wd, zqB[c], r.y);
                }
                *(ulonglong2*)&R4[slot] = r;
            }
        }
        __syncthreads();

        /* ---- issue iw[q+1] + ob[q+1] (w_s/ob_s free post-barrier) ---- */
        if (q + 1 < NQ) {
            STAGE32(sw_u, iw + ((size_t)(q + 1) << 13));
            STAGE4(sob_u, obias + ((size_t)(q + 1) << 10));
        }
        CPA_COMMIT();
    }

    /* ---- epilogue: qout = z*mask - r_final ---- */
    if (wout) {
        #pragma unroll
        for (int it = 0; it < 16; it++) {
            int i = tid + it * NTH;
            int d = i >> 3, tq = i & 7;
            float4 zv = *(const float4*)(zb + (size_t)d * TDIM + (tq << 2));
            float4 rv = R4[d * 8 + (tq ^ (d & 7))];
            int tb = t0 + (tq << 2);
            float4 o;
            o.x = ((tb + 0 < len) ? zv.x : 0.0f) - rv.x;
            o.y = ((tb + 1 < len) ? zv.y : 0.0f) - rv.y;
            o.z = ((tb + 2 < len) ? zv.z : 0.0f) - rv.z;
            o.w = ((tb + 3 < len) ? zv.w : 0.0f) - rv.w;
            *(float4*)(out + (size_t)b * DDIM * TDIM + (size_t)d * TDIM + t0 + (tq << 2)) = o;
        }
    }
    if (wlen && blockIdx.x == 0 && tid < BDIMS)
        out[BDT + NQBT + tid] = (float)inlen[tid];
}

extern "C" void kernel_launch(void* const* d_in, const int* in_sizes, int n_in,
                              void* d_out, int out_size)
{
    const float* z   = (const float*)d_in[0];
    const float* iw  = (const float*)d_in[1];
    const float* ib  = (const float*)d_in[2];
    const float* ow  = (const float*)d_in[3];
    const float* ob  = (const float*)d_in[4];
    const float* cbk = (const float*)d_in[5];
    const int* inlen = (const int*)d_in[6];
    float* out = (float*)d_out;

    cudaFuncSetAttribute(rvq_kernel, cudaFuncAttributeMaxDynamicSharedMemorySize, SM_BYTES);

    int wout = (out_size >= BDT) ? 1 : 0;
    int widx = (out_size >= BDT + NQBT) ? 1 : 0;
    int wlen = (out_size >= BDT + NQBT + BDIMS) ? 1 : 0;

    prep_kernel<<<256, 512>>>(ow, cbk);
    rvq_kernel<<<NCOLS / TILE, NTH, SM_BYTES>>>(z, iw, ib, ob, cbk, inlen,
                                               out, wout, widx, wlen);
}